// round 13
// baseline (speedup 1.0000x reference)
#include <cuda_runtime.h>
#include <cuda_bf16.h>
#include <math.h>
#include <stdint.h>

#define Dm     256
#define Kc     128
#define NTOK   131072
#define TM     64
#define NTILES (NTOK / TM)        // 2048
#define NTHR   256
#define NWARP  8
#define MAXCTA 512
#define QCAP   1024
#define MARG   0.035f             // >= 2.2x rigorous bf16 coarse-dot error bound

// output layout (float32, tuple order flattened+concatenated)
#define OFF_Q    ((size_t)1)
#define OFF_PERP ((size_t)1 + (size_t)NTOK * Dm)
#define OFF_ENC  (OFF_PERP + 1)
#define OFF_IDX  (OFF_ENC + (size_t)NTOK * Kc)

// ---- smem byte offsets ----
#define SROW    528                // 264 bf16/row, ldmatrix conflict-free
#define SM_B    0                  // bf16 B [128][264] = 67584
#define SM_E2   67584              // float[128]
#define SM_SIDX 68096              // int[64]
#define SM_CH   68352              // int[128]
#define SM_RFUL 68864              // int[64]
#define SM_QB   69120              // ull[64]
#define SM_RED  69632              // float[256]
#define SM_QL   70656              // int[QCAP] = 4096
#define SM_QCNT 74752
#define SM_TICK 74756
#define SM_ENM  74760
#define SM_TILE 74764
#define SMEM_BYTES 74880           // x3 CTAs = 224640 < 227KB carveout

__device__ int   g_hist[MAXCTA * Kc];
__device__ float g_partials[MAXCTA];
__device__ int   g_done = 0;
__device__ int   g_tile = 0;

__device__ __forceinline__ uint32_t smem_u32(const void* p) {
    uint32_t a;
    asm("{ .reg .u64 t; cvta.to.shared.u64 t, %1; cvt.u32.u64 %0, t; }" : "=r"(a) : "l"(p));
    return a;
}
__device__ __forceinline__ uint32_t packbf(float lo, float hi) {
    uint32_t r;
    asm("cvt.rn.bf16x2.f32 %0, %1, %2;" : "=r"(r) : "f"(hi), "f"(lo));
    return r;
}
__device__ __forceinline__ void sts64(uint32_t addr, uint32_t a, uint32_t b) {
    asm volatile("st.shared.v2.b32 [%0], {%1,%2};" :: "r"(addr), "r"(a), "r"(b) : "memory");
}
__device__ __forceinline__ void ldsm_x4(uint32_t& r0, uint32_t& r1, uint32_t& r2, uint32_t& r3, uint32_t addr) {
    asm volatile("ldmatrix.sync.aligned.m8n8.x4.shared.b16 {%0,%1,%2,%3}, [%4];"
                 : "=r"(r0), "=r"(r1), "=r"(r2), "=r"(r3) : "r"(addr));
}
__device__ __forceinline__ void mma_bf16(float* d, const uint32_t* a, uint32_t b0, uint32_t b1) {
    asm volatile(
        "mma.sync.aligned.m16n8k16.row.col.f32.bf16.bf16.f32 "
        "{%0,%1,%2,%3}, {%4,%5,%6,%7}, {%8,%9}, {%0,%1,%2,%3};"
        : "+f"(d[0]), "+f"(d[1]), "+f"(d[2]), "+f"(d[3])
        : "r"(a[0]), "r"(a[1]), "r"(a[2]), "r"(a[3]), "r"(b0), "r"(b1));
}
// sortable (dist,code) key: atomicMin -> min dist, ties -> min code
__device__ __forceinline__ unsigned long long packkey(float f, int code) {
    uint32_t b = __float_as_uint(f);
    b = (b & 0x80000000u) ? ~b : (b | 0x80000000u);
    return ((unsigned long long)b << 32) | (unsigned)code;
}

extern __shared__ char smem[];

__global__ void __launch_bounds__(NTHR, 3) vq_kernel(
    const float* __restrict__ inp,
    const float* __restrict__ emb,
    float* __restrict__ out,
    int ncta)
{
    const uint32_t sb = smem_u32(smem);
    float* e2s   = (float*)(smem + SM_E2);
    int*   sidx  = (int*)(smem + SM_SIDX);
    int*   chist = (int*)(smem + SM_CH);
    int*   rful  = (int*)(smem + SM_RFUL);
    unsigned long long* qbest = (unsigned long long*)(smem + SM_QB);
    float* red   = (float*)(smem + SM_RED);
    int*   qlist = (int*)(smem + SM_QL);
    int*   qcnt  = (int*)(smem + SM_QCNT);
    int*   tick  = (int*)(smem + SM_TICK);
    float* enmp  = (float*)(smem + SM_ENM);
    int*   tilep = (int*)(smem + SM_TILE);

    const int tid  = threadIdx.x;
    const int wid  = tid >> 5;
    const int lane = tid & 31;
    const int cta  = blockIdx.x;
    const int wg   = wid >> 1;          // token group: 16 tokens (4 groups = 64)
    const int hh   = wid & 1;           // code half: 64 codes

    if (tid < Kc) chist[tid] = 0;

    // ---- stage B = bf16(emb) (4 thr/row, 2 passes) + e2 ----
    #pragma unroll
    for (int pass = 0; pass < 2; pass++) {
        int row = (tid >> 2) + pass * 64;
        int part = tid & 3;
        const float* src = emb + row * Dm;
        uint32_t dst = sb + SM_B + row * SROW;
        float es = 0.f;
        #pragma unroll
        for (int j = 0; j < 16; j++) {
            int c4 = part + 4 * j;
            float4 v = *(const float4*)(src + c4 * 4);
            es = fmaf(v.x, v.x, es); es = fmaf(v.y, v.y, es);
            es = fmaf(v.z, v.z, es); es = fmaf(v.w, v.w, es);
            sts64(dst + c4 * 8, packbf(v.x, v.y), packbf(v.z, v.w));
        }
        es += __shfl_xor_sync(0xffffffffu, es, 1);
        es += __shfl_xor_sync(0xffffffffu, es, 2);
        if (part == 0) e2s[row] = es;
    }
    __syncthreads();
    if (tid < 32) {      // max ||e||
        float m = 0.f;
        #pragma unroll
        for (int j = 0; j < 4; j++) m = fmaxf(m, e2s[tid * 4 + j]);
        #pragma unroll
        for (int s = 16; s > 0; s >>= 1) m = fmaxf(m, __shfl_xor_sync(0xffffffffu, m, s));
        if (tid == 0) enmp[0] = sqrtf(m);
    }
    __syncthreads();
    const float enm = enmp[0];

    const uint32_t b_addr0 = sb + SM_B +
        (uint32_t)(hh * 64 + (lane & 7) + ((lane >> 4) & 1) * 8) * SROW + ((lane >> 3) & 1) * 16;

    float lsum = 0.f;

    // ================= dynamic-tile loop =================
    for (;;) {
        if (tid == 0) { tilep[0] = atomicAdd(&g_tile, 1); qcnt[0] = 0; }
        if (tid < TM) { rful[tid] = 0; qbest[tid] = ~0ull; }
        __syncthreads();
        const int tile = tilep[0];
        if (tile >= NTILES) break;
        const int tb = tile * TM;

        // ---- coarse GEMM: A fragments straight from global (bf16 cvt in regs) ----
        const int rr0 = tb + wg * 16 + (lane >> 2);
        const float* xr0 = inp + (size_t)rr0 * Dm + (lane & 3) * 2;
        const float* xr1 = xr0 + 8 * Dm;
        float d[8][4];
        #pragma unroll
        for (int nt = 0; nt < 8; nt++)
            #pragma unroll
            for (int j = 0; j < 4; j++) d[nt][j] = 0.f;
        float xs0 = 0.f, xs1 = 0.f;

        #pragma unroll 4
        for (int ks = 0; ks < 16; ks++) {
            float2 v00 = *(const float2*)(xr0 + ks * 16);
            float2 v01 = *(const float2*)(xr0 + ks * 16 + 8);
            float2 v10 = *(const float2*)(xr1 + ks * 16);
            float2 v11 = *(const float2*)(xr1 + ks * 16 + 8);
            xs0 = fmaf(v00.x, v00.x, xs0); xs0 = fmaf(v00.y, v00.y, xs0);
            xs0 = fmaf(v01.x, v01.x, xs0); xs0 = fmaf(v01.y, v01.y, xs0);
            xs1 = fmaf(v10.x, v10.x, xs1); xs1 = fmaf(v10.y, v10.y, xs1);
            xs1 = fmaf(v11.x, v11.x, xs1); xs1 = fmaf(v11.y, v11.y, xs1);
            uint32_t a[4];
            a[0] = packbf(v00.x, v00.y);
            a[1] = packbf(v10.x, v10.y);
            a[2] = packbf(v01.x, v01.y);
            a[3] = packbf(v11.x, v11.y);
            #pragma unroll
            for (int nt2 = 0; nt2 < 4; nt2++) {
                uint32_t b0, b1, b2, b3;
                ldsm_x4(b0, b1, b2, b3, b_addr0 + (uint32_t)(nt2 * 16) * SROW + ks * 32);
                mma_bf16(d[2 * nt2],     a, b0, b1);
                mma_bf16(d[2 * nt2 + 1], a, b2, b3);
            }
        }
        // full ||x||^2 for rows r0/r1 (quad covers all 256 cols)
        xs0 += __shfl_xor_sync(0xffffffffu, xs0, 1);
        xs0 += __shfl_xor_sync(0xffffffffu, xs0, 2);
        xs1 += __shfl_xor_sync(0xffffffffu, xs1, 1);
        xs1 += __shfl_xor_sync(0xffffffffu, xs1, 2);

        // ---- bound pass: warp-local half-best + margin, enqueue candidates ----
        {
            const int r0 = wg * 16 + (lane >> 2);
            const int r1 = r0 + 8;
            float b0v = 3.4e38f, b1v = 3.4e38f;
            #pragma unroll
            for (int nt = 0; nt < 8; nt++) {
                int cb = hh * 64 + nt * 8 + 2 * (lane & 3);
                float e0 = e2s[cb], e1 = e2s[cb + 1];
                b0v = fminf(b0v, fminf(fmaf(-2.f, d[nt][0], e0), fmaf(-2.f, d[nt][1], e1)));
                b1v = fminf(b1v, fminf(fmaf(-2.f, d[nt][2], e0), fmaf(-2.f, d[nt][3], e1)));
            }
            #pragma unroll
            for (int m = 1; m < 4; m <<= 1) {
                b0v = fminf(b0v, __shfl_xor_sync(0xffffffffu, b0v, m));
                b1v = fminf(b1v, __shfl_xor_sync(0xffffffffu, b1v, m));
            }
            const float t0 = b0v + 2.f * MARG * sqrtf(xs0) * enm;
            const float t1 = b1v + 2.f * MARG * sqrtf(xs1) * enm;

            int c0 = 0, c1 = 0;
            #pragma unroll
            for (int nt = 0; nt < 8; nt++) {
                int cb = hh * 64 + nt * 8 + 2 * (lane & 3);
                float e0 = e2s[cb], e1 = e2s[cb + 1];
                if (fmaf(-2.f, d[nt][0], e0) <= t0) c0++;
                if (fmaf(-2.f, d[nt][1], e1) <= t0) c0++;
                if (fmaf(-2.f, d[nt][2], e0) <= t1) c1++;
                if (fmaf(-2.f, d[nt][3], e1) <= t1) c1++;
            }
            int tot = c0 + c1;
            if (tot > 0) {
                int pos = atomicAdd(qcnt, tot);
                if (pos + tot > QCAP) {
                    rful[r0] = 1; rful[r1] = 1;
                } else {
                    #pragma unroll
                    for (int nt = 0; nt < 8; nt++) {
                        int cb = hh * 64 + nt * 8 + 2 * (lane & 3);
                        float e0 = e2s[cb], e1 = e2s[cb + 1];
                        if (fmaf(-2.f, d[nt][0], e0) <= t0) qlist[pos++] = (r0 << 8) | cb;
                        if (fmaf(-2.f, d[nt][1], e1) <= t0) qlist[pos++] = (r0 << 8) | (cb + 1);
                        if (fmaf(-2.f, d[nt][2], e0) <= t1) qlist[pos++] = (r1 << 8) | cb;
                        if (fmaf(-2.f, d[nt][3], e1) <= t1) qlist[pos++] = (r1 << 8) | (cb + 1);
                    }
                }
            }
        }
        __syncthreads();

        // ---- exact refine: warp per candidate (fp32, L2-hot) ----
        {
            int nq = qcnt[0]; if (nq > QCAP) nq = QCAP;
            for (int q = wid; q < nq; q += NWARP) {
                int ent = qlist[q];
                int tok = ent >> 8, code = ent & 255;
                const float* xr = inp + (size_t)(tb + tok) * Dm + lane * 8;
                const float* er = emb + (size_t)code * Dm + lane * 8;
                float4 xa = *(const float4*)(xr),  xb2 = *(const float4*)(xr + 4);
                float4 ea = *(const float4*)(er),  eb2 = *(const float4*)(er + 4);
                float dt = xa.x * ea.x;
                dt = fmaf(xa.y, ea.y, dt); dt = fmaf(xa.z, ea.z, dt); dt = fmaf(xa.w, ea.w, dt);
                dt = fmaf(xb2.x, eb2.x, dt); dt = fmaf(xb2.y, eb2.y, dt);
                dt = fmaf(xb2.z, eb2.z, dt); dt = fmaf(xb2.w, eb2.w, dt);
                #pragma unroll
                for (int m = 16; m > 0; m >>= 1) dt += __shfl_xor_sync(0xffffffffu, dt, m);
                if (lane == 0) {
                    float dist = fmaf(-2.f, dt, e2s[code]);
                    atomicMin(&qbest[tok], packkey(dist, code));
                }
            }
            // overflow fallback (expected never): exact full scan
            for (int r = wid; r < TM; r += NWARP) if (rful[r]) {
                float bv = 3.4e38f; int bi = 0;
                for (int cc = 0; cc < 4; cc++) {
                    int code = lane + cc * 32;
                    const float* xr = inp + (size_t)(tb + r) * Dm;
                    const float* er = emb + (size_t)code * Dm;
                    float dt = 0.f;
                    for (int i = 0; i < 64; i++) {
                        float4 xv = *(const float4*)(xr + i * 4);
                        float4 ev = *(const float4*)(er + i * 4);
                        dt = fmaf(xv.x, ev.x, dt); dt = fmaf(xv.y, ev.y, dt);
                        dt = fmaf(xv.z, ev.z, dt); dt = fmaf(xv.w, ev.w, dt);
                    }
                    float dist = fmaf(-2.f, dt, e2s[code]);
                    if (dist < bv || (dist == bv && code < bi)) { bv = dist; bi = code; }
                }
                #pragma unroll
                for (int m = 1; m < 32; m <<= 1) {
                    float ov = __shfl_xor_sync(0xffffffffu, bv, m);
                    int   oi = __shfl_xor_sync(0xffffffffu, bi, m);
                    if (ov < bv || (ov == bv && oi < bi)) { bv = ov; bi = oi; }
                }
                if (lane == 0) sidx[r] = bi;
            }
        }
        __syncthreads();

        if (tid < TM) {
            if (!rful[tid]) sidx[tid] = (int)(qbest[tid] & 0xFFu);
            atomicAdd(&chist[sidx[tid]], 1);
        }
        __syncthreads();

        // ---- quantized + exact loss (region starts at elem 1 -> scalar stores) ----
        float* out_q = out + OFF_Q;
        #pragma unroll 1
        for (int i = tid; i < TM * (Dm / 4); i += NTHR) {   // 16 iters
            int tok = i >> 6, f4 = i & 63;
            int k2 = sidx[tok];
            float4 e = *(const float4*)(emb + (size_t)k2 * Dm + f4 * 4);
            float4 x = *(const float4*)(inp + (size_t)(tb + tok) * Dm + f4 * 4);
            float* qp = out_q + (size_t)(tb + tok) * Dm + f4 * 4;
            qp[0] = e.x; qp[1] = e.y; qp[2] = e.z; qp[3] = e.w;
            float dx = e.x - x.x, dy = e.y - x.y, dz = e.z - x.z, dw = e.w - x.w;
            lsum += dx * dx + dy * dy + dz * dz + dw * dw;
        }

        // ---- one-hot encodings (region start == 2 mod 4 -> float2 ok) ----
        float* out_e = out + OFF_ENC;
        #pragma unroll 1
        for (int i = tid; i < TM * (Kc / 4); i += NTHR) {   // 8 iters
            int tok = i >> 5, f4 = i & 31;
            int k2 = sidx[tok];
            int d0 = f4 * 4;
            float2 v01, v23;
            v01.x = (d0 + 0 == k2) ? 1.f : 0.f;
            v01.y = (d0 + 1 == k2) ? 1.f : 0.f;
            v23.x = (d0 + 2 == k2) ? 1.f : 0.f;
            v23.y = (d0 + 3 == k2) ? 1.f : 0.f;
            float* ep = out_e + (size_t)(tb + tok) * Kc + d0;
            *(float2*)(ep)     = v01;
            *(float2*)(ep + 2) = v23;
        }

        if (tid < TM) out[OFF_IDX + tb + tid] = (float)sidx[tid];
        // loop-top sync separates sidx readers from next-tile writers
    }

    // ================= per-CTA results =================
    red[tid] = lsum;
    __syncthreads();
    #pragma unroll
    for (int s = NTHR / 2; s > 0; s >>= 1) {
        if (tid < s) red[tid] += red[tid + s];
        __syncthreads();
    }
    if (tid == 0) g_partials[cta] = red[0];
    if (tid < Kc) g_hist[cta * Kc + tid] = chist[tid];

    __syncthreads();
    __threadfence();
    if (tid == 0) tick[0] = atomicAdd(&g_done, 1);
    __syncthreads();

    // ================= last CTA: loss + perplexity =================
    if (tick[0] == ncta - 1) {
        __threadfence();
        float term = 0.f;
        if (tid < Kc) {
            int cnt = 0;
            for (int b = 0; b < ncta; b++) cnt += g_hist[b * Kc + tid];
            float p = (float)cnt / (float)NTOK;
            term = p * logf(p + 1e-10f);
        }
        red[tid] = term;
        __syncthreads();
        #pragma unroll
        for (int s = NTHR / 2; s > 0; s >>= 1) {
            if (tid < s) red[tid] += red[tid + s];
            __syncthreads();
        }
        float perp = expf(-red[0]);
        __syncthreads();

        float ps = 0.f;
        for (int b = tid; b < ncta; b += NTHR) ps += g_partials[b];
        red[tid] = ps;
        __syncthreads();
        #pragma unroll
        for (int s = NTHR / 2; s > 0; s >>= 1) {
            if (tid < s) red[tid] += red[tid + s];
            __syncthreads();
        }
        if (tid == 0) {
            out[0]        = 0.25f * red[0] / ((float)NTOK * (float)Dm);
            out[OFF_PERP] = perp;
            g_done = 0;          // reset for next graph replay
            g_tile = 0;
        }
    }
}

// ---------------- launch ----------------
extern "C" void kernel_launch(void* const* d_in, const int* in_sizes, int n_in,
                              void* d_out, int out_size) {
    const float* inp = (const float*)d_in[0];   // [64,2048,256] f32
    const float* emb = (const float*)d_in[1];   // [128,256]     f32
    float* out = (float*)d_out;

    int nsm = 0;
    cudaDeviceGetAttribute(&nsm, cudaDevAttrMultiProcessorCount, 0);
    if (nsm <= 0) nsm = 148;
    int ncta = nsm * 3;
    if (ncta > MAXCTA) ncta = MAXCTA;
    if (ncta > NTILES) ncta = NTILES;

    cudaFuncSetAttribute(vq_kernel,
                         cudaFuncAttributeMaxDynamicSharedMemorySize, SMEM_BYTES);

    vq_kernel<<<ncta, NTHR, SMEM_BYTES>>>(inp, emb, out, ncta);
}